// round 2
// baseline (speedup 1.0000x reference)
#include <cuda_runtime.h>
#include <cstddef>

#define Bk 32
#define Nk 1535
#define NN 1536
#define Hk 64

// Scratch (no allocations allowed -> __device__ globals)
__device__ float g_h[(size_t)Bk * Hk * NN];   // [b][h][j]  ~12.6 MB
__device__ float g_sk[Bk * NN];
__device__ float g_w[Bk * NN];
__device__ float g_m[Bk * Hk];
__device__ float g_kvec[Hk];
__device__ float g_skb[1];

// ---------------------------------------------------------------------------
// K0: fold K-projection + QK k-half into a single vector:
//     sk[j,b] = nodes[j,b] . kvec + skb,  kvec[h] = sum_h' WK[h',h]*wQKk[h']
// ---------------------------------------------------------------------------
__global__ void k0_prep(const float* __restrict__ WK,
                        const float* __restrict__ bK,
                        const float* __restrict__ wQKk) {
    int o = threadIdx.x;  // 64 threads
    float acc = 0.f;
    #pragma unroll 8
    for (int hp = 0; hp < Hk; hp++) acc += WK[hp * Hk + o] * wQKk[hp];
    g_kvec[o] = acc;
    if (o == 0) {
        float s = 0.f;
        for (int h = 0; h < Hk; h++) s += bK[h] * wQKk[h];
        g_skb[0] = s;
    }
}

// ---------------------------------------------------------------------------
// K1: encoder MLP per (b, node j) + sk dot.  grid (6, 32), 256 thr.
//     j == Nk is the output node (single-layer enc_new_x path).
//     Writes h to [b][h][j] layout (coalesced over j).
//     W2 smem reads are warp-uniform -> broadcast (no crossbar pressure);
//     kernel is FFMA-issue bound.
// ---------------------------------------------------------------------------
__global__ __launch_bounds__(256) void k1_encode(
    const float* __restrict__ xx,   // [B,N,8]
    const float* __restrict__ yy,   // [B,N]
    const float* __restrict__ oxx,  // [B,1,8]
    const float* __restrict__ W1, const float* __restrict__ b1,
    const float* __restrict__ W2, const float* __restrict__ b2,
    const float* __restrict__ Wenc, const float* __restrict__ benc) {
    __shared__ float W1T[9 * Hk];     // [i][o]
    __shared__ float W2s[Hk * Hk];    // [o][i]
    __shared__ float WencT[8 * Hk];   // [i][o]
    __shared__ float b1s[Hk], b2s[Hk], kvs[Hk], bencs[Hk];

    const int tid = threadIdx.x;
    const int b = blockIdx.y;

    for (int t = tid; t < 9 * Hk; t += 256) { int o = t / 9, i = t % 9; W1T[i * Hk + o] = W1[t]; }
    for (int t = tid; t < 8 * Hk; t += 256) { int o = t / 8, i = t % 8; WencT[i * Hk + o] = Wenc[t]; }
    for (int t = tid; t < Hk * Hk; t += 256) W2s[t] = W2[t];
    if (tid < Hk) { b1s[tid] = b1[tid]; b2s[tid] = b2[tid]; kvs[tid] = g_kvec[tid]; bencs[tid] = benc[tid]; }
    __syncthreads();

    const int j = blockIdx.x * 256 + tid;

    if (j < Nk) {
        float x[9];
        const float* xp = xx + ((size_t)b * Nk + j) * 8;
        #pragma unroll
        for (int i = 0; i < 8; i++) x[i] = xp[i];
        x[8] = yy[b * Nk + j];

        float h1[Hk];
        #pragma unroll
        for (int o = 0; o < Hk; o++) h1[o] = b1s[o];
        #pragma unroll
        for (int i = 0; i < 9; i++) {
            const float xi = x[i];
            const float4* w4 = (const float4*)(W1T + i * Hk);
            #pragma unroll
            for (int o4 = 0; o4 < 16; o4++) {
                float4 w = w4[o4];
                h1[4 * o4 + 0] += w.x * xi; h1[4 * o4 + 1] += w.y * xi;
                h1[4 * o4 + 2] += w.z * xi; h1[4 * o4 + 3] += w.w * xi;
            }
        }
        #pragma unroll
        for (int o = 0; o < Hk; o++) h1[o] = fmaxf(h1[o], 0.f);

        float skacc = g_skb[0];
        float* hout = g_h + (size_t)b * Hk * NN + j;
        #pragma unroll 4
        for (int o = 0; o < Hk; o++) {
            float acc = b2s[o];
            const float4* w4 = (const float4*)(W2s + o * Hk);
            #pragma unroll
            for (int i4 = 0; i4 < 16; i4++) {
                float4 w = w4[i4];
                acc += w.x * h1[4 * i4] + w.y * h1[4 * i4 + 1]
                     + w.z * h1[4 * i4 + 2] + w.w * h1[4 * i4 + 3];
            }
            acc = fmaxf(acc, 0.f);
            hout[(size_t)o * NN] = acc;
            skacc += acc * kvs[o];
        }
        g_sk[b * NN + j] = skacc;
    } else if (j == Nk) {
        // output node: relu(Wenc @ output_xx[b,0,:] + benc)
        float x[8];
        const float* xp = oxx + b * 8;
        #pragma unroll
        for (int i = 0; i < 8; i++) x[i] = xp[i];
        float skacc = g_skb[0];
        float* hout = g_h + (size_t)b * Hk * NN + j;
        #pragma unroll
        for (int o = 0; o < Hk; o++) {
            float acc = bencs[o];
            #pragma unroll
            for (int i = 0; i < 8; i++) acc += WencT[i * Hk + o] * x[i];
            acc = fmaxf(acc, 0.f);
            hout[(size_t)o * NN] = acc;
            skacc += acc * kvs[o];
        }
        g_sk[b * NN + j] = skacc;
    }
}

// ---------------------------------------------------------------------------
// K2: per-batch softmax over 1536 sk values.  grid 32, 256 thr.
// ---------------------------------------------------------------------------
__global__ __launch_bounds__(256) void k2_softmax() {
    const int b = blockIdx.x, tid = threadIdx.x;
    __shared__ float red[256];
    float vals[6];
    float mx = -1e30f;
    #pragma unroll
    for (int t = 0; t < 6; t++) {
        vals[t] = g_sk[b * NN + t * 256 + tid];
        mx = fmaxf(mx, vals[t]);
    }
    red[tid] = mx; __syncthreads();
    for (int s = 128; s > 0; s >>= 1) {
        if (tid < s) red[tid] = fmaxf(red[tid], red[tid + s]);
        __syncthreads();
    }
    mx = red[0]; __syncthreads();
    float sum = 0.f;
    #pragma unroll
    for (int t = 0; t < 6; t++) { vals[t] = __expf(vals[t] - mx); sum += vals[t]; }
    red[tid] = sum; __syncthreads();
    for (int s = 128; s > 0; s >>= 1) {
        if (tid < s) red[tid] += red[tid + s];
        __syncthreads();
    }
    const float inv = 1.f / red[0];
    #pragma unroll
    for (int t = 0; t < 6; t++) g_w[b * NN + t * 256 + tid] = vals[t] * inv;
}

// ---------------------------------------------------------------------------
// K3: m[b][o] = sum_j w[b][j] * h[b][o][j].  grid (64, 32), 256 thr.
//     Streams 12.6 MB + 0.4 MB -> HBM-bound, ~3 us.
// ---------------------------------------------------------------------------
__global__ __launch_bounds__(256) void k3_reduce() {
    const int o = blockIdx.x, b = blockIdx.y, tid = threadIdx.x;
    const float* hp = g_h + ((size_t)b * Hk + o) * NN;
    const float* wp = g_w + b * NN;
    float acc = 0.f;
    #pragma unroll
    for (int t = tid; t < NN; t += 256) acc += hp[t] * wp[t];
    __shared__ float red[8];
    for (int s = 16; s > 0; s >>= 1) acc += __shfl_down_sync(0xffffffffu, acc, s);
    if ((tid & 31) == 0) red[tid >> 5] = acc;
    __syncthreads();
    if (tid < 8) {
        acc = red[tid];
        for (int s = 4; s > 0; s >>= 1) acc += __shfl_down_sync(0xffu, acc, s);
        if (tid == 0) g_m[b * Hk + o] = acc;
    }
}

// ---------------------------------------------------------------------------
// K4: collapsed rounds, single block, 512 threads.
//     Round 1: c = m@WV^T+bV; z = c@WA^T+bA; BN; relu.
//     Rounds 2-4 (identical nodes, uniform attention): v = n@WV^T+bV;
//     z = v@WA^T+bA; BN; relu.  Then heads (max over identical nodes = n).
//
//     Weights staged ONCE to smem, transposed [o][h] with row pad 65 words:
//       - per-o weight read: lanes = consecutive h -> conflict-free
//       - ns[b][o] float4 read: warp-uniform -> broadcast (1 cyc/wavefront)
//     Thread t -> h = t&63, batch group bg = t>>6 handles b = bg + 8k, k<4.
// ---------------------------------------------------------------------------
__global__ __launch_bounds__(512) void k4_tail(
    const float* __restrict__ WV, const float* __restrict__ bV,
    const float* __restrict__ WA, const float* __restrict__ bA,
    const float* __restrict__ gamma, const float* __restrict__ beta,
    const float* __restrict__ Wmu, const float* __restrict__ bmu,
    const float* __restrict__ Wsig, const float* __restrict__ bsig,
    float* __restrict__ out) {
    __shared__ float WvT[Hk * 65];   // [o][h], pad 65 -> conflict-free both ways
    __shared__ float WaT[Hk * 65];
    __shared__ float ns[Bk * Hk];    // [b][h]
    __shared__ float sc[Hk], sh[Hk];
    __shared__ float bvs[Hk], bas[Hk];

    const int tid = threadIdx.x;
    const int h = tid & 63;
    const int bg = tid >> 6;         // 0..7

    // Stage weights transposed (stores: addr = c*65 + r, lanes vary c -> banks
    // (65c)%32 = c%32 distinct -> conflict-free).
    for (int t = tid; t < Hk * Hk; t += 512) {
        int r = t >> 6, c = t & 63;  // W[r][c]
        WvT[c * 65 + r] = WV[t];
        WaT[c * 65 + r] = WA[t];
    }
    if (tid < Hk) { bvs[tid] = bV[tid]; bas[tid] = bA[tid]; }
    for (int t = tid; t < Bk * Hk; t += 512) ns[t] = g_m[t];
    __syncthreads();

    const int b0 = bg, b1 = bg + 8, b2 = bg + 16, b3 = bg + 24;
    float z0, z1, z2, z3;

    for (int r = 0; r < 4; r++) {
        // ---- gemm1: v[b][h] = ns[b][:] . WV[h][:] + bV[h]
        float a0 = bvs[h], a1 = bvs[h], a2 = bvs[h], a3 = bvs[h];
        #pragma unroll
        for (int o4 = 0; o4 < 16; o4++) {
            float4 n0 = *(const float4*)(ns + b0 * Hk + o4 * 4);
            float4 n1 = *(const float4*)(ns + b1 * Hk + o4 * 4);
            float4 n2 = *(const float4*)(ns + b2 * Hk + o4 * 4);
            float4 n3 = *(const float4*)(ns + b3 * Hk + o4 * 4);
            #pragma unroll
            for (int c = 0; c < 4; c++) {
                float w = WvT[(o4 * 4 + c) * 65 + h];
                a0 += (&n0.x)[c] * w; a1 += (&n1.x)[c] * w;
                a2 += (&n2.x)[c] * w; a3 += (&n3.x)[c] * w;
            }
        }
        __syncthreads();
        ns[b0 * Hk + h] = a0; ns[b1 * Hk + h] = a1;
        ns[b2 * Hk + h] = a2; ns[b3 * Hk + h] = a3;
        __syncthreads();

        // ---- gemm2: z[b][h] = v[b][:] . WA[h][:] + bA[h]
        z0 = bas[h]; z1 = bas[h]; z2 = bas[h]; z3 = bas[h];
        #pragma unroll
        for (int o4 = 0; o4 < 16; o4++) {
            float4 n0 = *(const float4*)(ns + b0 * Hk + o4 * 4);
            float4 n1 = *(const float4*)(ns + b1 * Hk + o4 * 4);
            float4 n2 = *(const float4*)(ns + b2 * Hk + o4 * 4);
            float4 n3 = *(const float4*)(ns + b3 * Hk + o4 * 4);
            #pragma unroll
            for (int c = 0; c < 4; c++) {
                float w = WaT[(o4 * 4 + c) * 65 + h];
                z0 += (&n0.x)[c] * w; z1 += (&n1.x)[c] * w;
                z2 += (&n2.x)[c] * w; z3 += (&n3.x)[c] * w;
            }
        }
        __syncthreads();
        ns[b0 * Hk + h] = z0; ns[b1 * Hk + h] = z1;
        ns[b2 * Hk + h] = z2; ns[b3 * Hk + h] = z3;
        __syncthreads();

        // ---- BatchNorm over batch (training mode, biased var)
        if (tid < Hk) {
            float s = 0.f, ss = 0.f;
            #pragma unroll 8
            for (int b = 0; b < Bk; b++) { float v = ns[b * Hk + tid]; s += v; ss += v * v; }
            float mu = s * (1.f / Bk);
            float var = ss * (1.f / Bk) - mu * mu;
            float scale = gamma[tid] * rsqrtf(var + 1e-5f);
            sc[tid] = scale;
            sh[tid] = beta[tid] - mu * scale;
        }
        __syncthreads();
        ns[b0 * Hk + h] = fmaxf(z0 * sc[h] + sh[h], 0.f);
        ns[b1 * Hk + h] = fmaxf(z1 * sc[h] + sh[h], 0.f);
        ns[b2 * Hk + h] = fmaxf(z2 * sc[h] + sh[h], 0.f);
        ns[b3 * Hk + h] = fmaxf(z3 * sc[h] + sh[h], 0.f);
        __syncthreads();
    }

    // Heads: agg = n (max over identical nodes)
    if (tid < Bk) {
        float m = bmu[0], s = bsig[0];
        #pragma unroll 8
        for (int hh = 0; hh < Hk; hh++) {
            float v = ns[tid * Hk + hh];
            m += v * Wmu[hh]; s += v * Wsig[hh];
        }
        out[tid] = m;
        out[Bk + tid] = s * s + 0.01f;
    }
}

// ---------------------------------------------------------------------------
extern "C" void kernel_launch(void* const* d_in, const int* in_sizes, int n_in,
                              void* d_out, int out_size) {
    const float* xx   = (const float*)d_in[0];   // input_xx  [32,1535,8]
    const float* yy   = (const float*)d_in[1];   // input_yy  [32,1535]
    const float* oxx  = (const float*)d_in[2];   // output_xx [32,1,8]
    const float* W1   = (const float*)d_in[3];
    const float* b1   = (const float*)d_in[4];
    const float* W2   = (const float*)d_in[5];
    const float* b2   = (const float*)d_in[6];
    const float* Wenc = (const float*)d_in[7];
    const float* benc = (const float*)d_in[8];
    // d_in[9], d_in[10] = WQ, bQ  (cancel in softmax -> unused)
    const float* WK   = (const float*)d_in[11];
    const float* bK   = (const float*)d_in[12];
    const float* WV   = (const float*)d_in[13];
    const float* bV   = (const float*)d_in[14];
    // d_in[15] = wQKq (cancels), d_in[17] = bQK (cancels)
    const float* wQKk = (const float*)d_in[16];
    const float* WA   = (const float*)d_in[18];
    const float* bA   = (const float*)d_in[19];
    const float* gamma= (const float*)d_in[20];
    const float* beta = (const float*)d_in[21];
    const float* Wmu  = (const float*)d_in[22];
    const float* bmu  = (const float*)d_in[23];
    const float* Wsig = (const float*)d_in[24];
    const float* bsig = (const float*)d_in[25];
    float* out = (float*)d_out;

    k0_prep<<<1, 64>>>(WK, bK, wQKk);
    dim3 g1(6, 32);
    k1_encode<<<g1, 256>>>(xx, yy, oxx, W1, b1, W2, b2, Wenc, benc);
    k2_softmax<<<32, 256>>>();
    dim3 g3(64, 32);
    k3_reduce<<<g3, 256>>>();
    k4_tail<<<1, 512>>>(WV, bV, WA, bA, gamma, beta, Wmu, bmu, Wsig, bsig, out);
}

// round 3
// speedup vs baseline: 1.0356x; 1.0356x over previous
#include <cuda_runtime.h>
#include <cstddef>

#define Bk 32
#define Nk 1535
#define NN 1536
#define Hk 64

// Scratch (no allocations allowed -> __device__ globals)
__device__ float g_h[(size_t)Bk * Hk * NN];   // [b][h][j]  ~12.6 MB
__device__ float g_sk[Bk * NN];
__device__ float g_m[Bk * Hk];
__device__ float g_kvec[Hk];
__device__ float g_skb[1];
__device__ float g_Wc[Hk * Hk];               // WA @ WV
__device__ float g_bc[Hk];                    // WA @ bV + bA

// ---- packed f32x2 helpers (sm_10x FFMA2; per-lane rounding == scalar FMA) ----
__device__ __forceinline__ unsigned long long fma2(unsigned long long a,
                                                   unsigned long long b,
                                                   unsigned long long c) {
    unsigned long long d;
    asm("fma.rn.f32x2 %0, %1, %2, %3;" : "=l"(d) : "l"(a), "l"(b), "l"(c));
    return d;
}
__device__ __forceinline__ unsigned long long pack2(float lo, float hi) {
    unsigned long long d;
    asm("mov.b64 %0, {%1, %2};" : "=l"(d) : "f"(lo), "f"(hi));
    return d;
}
__device__ __forceinline__ float2 unpack2(unsigned long long v) {
    float2 r;
    asm("mov.b64 {%0, %1}, %2;" : "=f"(r.x), "=f"(r.y) : "l"(v));
    return r;
}

// ---------------------------------------------------------------------------
// K0: kvec = WK^T wQKk, skb = bK.wQKk, Wc = WA@WV, bc = WA@bV + bA.
//     One block, 1024 threads. ~1.5us.
// ---------------------------------------------------------------------------
__global__ __launch_bounds__(1024) void k0_prep(
    const float* __restrict__ WK, const float* __restrict__ bK,
    const float* __restrict__ wQKk,
    const float* __restrict__ WA, const float* __restrict__ bA,
    const float* __restrict__ WV, const float* __restrict__ bV) {
    __shared__ float WAs[Hk * Hk];
    __shared__ float WVs[Hk * Hk];
    __shared__ float wqk[Hk], bVs[Hk];
    const int tid = threadIdx.x;

    for (int t = tid; t < Hk * Hk; t += 1024) { WAs[t] = WA[t]; WVs[t] = WV[t]; }
    if (tid < Hk) { wqk[tid] = wQKk[tid]; bVs[tid] = bV[tid]; }
    __syncthreads();

    if (tid < Hk) {
        float acc = 0.f;
        #pragma unroll 8
        for (int hp = 0; hp < Hk; hp++) acc += WK[hp * Hk + tid] * wqk[hp];
        g_kvec[tid] = acc;
    } else if (tid == Hk) {
        float s = 0.f;
        for (int h = 0; h < Hk; h++) s += bK[h] * wqk[h];
        g_skb[0] = s;
    } else if (tid >= 128 && tid < 128 + Hk) {
        const int h = tid - 128;
        float acc = bA[h];
        #pragma unroll 8
        for (int k = 0; k < Hk; k++) acc += WAs[h * Hk + k] * bVs[k];
        g_bc[h] = acc;
    }

    // Wc[r][c] = sum_k WA[r][k] * WV[k][c]
    for (int e = tid; e < Hk * Hk; e += 1024) {
        const int r = e >> 6, c = e & 63;
        float acc = 0.f;
        #pragma unroll 8
        for (int k = 0; k < Hk; k++) acc += WAs[r * Hk + k] * WVs[k * Hk + c];
        g_Wc[e] = acc;
    }
}

// ---------------------------------------------------------------------------
// K1: encoder MLP per (b, node j) + sk dot.  grid (12, 32), 128 thr.
//     FFMA2-packed over output pairs; weights via LDS128 broadcast.
//     Writes h to [b][h][j] layout (coalesced over j).
// ---------------------------------------------------------------------------
__global__ __launch_bounds__(128) void k1_encode(
    const float* __restrict__ xx,   // [B,N,8]
    const float* __restrict__ yy,   // [B,N]
    const float* __restrict__ oxx,  // [B,1,8]
    const float* __restrict__ W1, const float* __restrict__ b1,
    const float* __restrict__ W2, const float* __restrict__ b2,
    const float* __restrict__ Wenc, const float* __restrict__ benc) {
    __shared__ __align__(16) float W1T[9 * Hk];    // [i][o]
    __shared__ __align__(16) float W2T[Hk * Hk];   // [i][o] (transposed)
    __shared__ __align__(16) float WencT[8 * Hk];  // [i][o]
    __shared__ __align__(16) float b1s[Hk];
    __shared__ __align__(16) float b2s[Hk];
    __shared__ float kvs[Hk], bencs[Hk];

    const int tid = threadIdx.x;
    const int b = blockIdx.y;

    for (int t = tid; t < 9 * Hk; t += 128) { int o = t / 9, i = t % 9; W1T[i * Hk + o] = W1[t]; }
    for (int t = tid; t < 8 * Hk; t += 128) { int o = t / 8, i = t % 8; WencT[i * Hk + o] = Wenc[t]; }
    for (int t = tid; t < Hk * Hk; t += 128) { int o = t >> 6, i = t & 63; W2T[i * Hk + o] = W2[t]; }
    if (tid < Hk) { b1s[tid] = b1[tid]; b2s[tid] = b2[tid]; kvs[tid] = g_kvec[tid]; bencs[tid] = benc[tid]; }
    __syncthreads();

    const int j = blockIdx.x * 128 + tid;

    if (j < Nk) {
        float x[9];
        const float4* xp = (const float4*)(xx + ((size_t)b * Nk + j) * 8);
        float4 xa = xp[0], xb4 = xp[1];
        x[0] = xa.x; x[1] = xa.y; x[2] = xa.z; x[3] = xa.w;
        x[4] = xb4.x; x[5] = xb4.y; x[6] = xb4.z; x[7] = xb4.w;
        x[8] = yy[b * Nk + j];

        // ---- layer 1 (packed o-pairs) ----
        unsigned long long h1p[32];
        {
            const ulonglong2* bp = (const ulonglong2*)b1s;
            #pragma unroll
            for (int q = 0; q < 16; q++) { ulonglong2 v = bp[q]; h1p[2 * q] = v.x; h1p[2 * q + 1] = v.y; }
        }
        #pragma unroll
        for (int i = 0; i < 9; i++) {
            const unsigned long long xbp = pack2(x[i], x[i]);
            const ulonglong2* wr = (const ulonglong2*)(W1T + i * Hk);
            #pragma unroll
            for (int q = 0; q < 16; q++) {
                ulonglong2 wv = wr[q];
                h1p[2 * q]     = fma2(wv.x, xbp, h1p[2 * q]);
                h1p[2 * q + 1] = fma2(wv.y, xbp, h1p[2 * q + 1]);
            }
        }
        float h1[Hk];
        #pragma unroll
        for (int q = 0; q < 32; q++) {
            float2 v = unpack2(h1p[q]);
            h1[2 * q] = fmaxf(v.x, 0.f);
            h1[2 * q + 1] = fmaxf(v.y, 0.f);
        }

        // ---- layer 2 (packed o-pairs, accumulation order per-o == scalar) ----
        unsigned long long acc[32];
        {
            const ulonglong2* bp = (const ulonglong2*)b2s;
            #pragma unroll
            for (int q = 0; q < 16; q++) { ulonglong2 v = bp[q]; acc[2 * q] = v.x; acc[2 * q + 1] = v.y; }
        }
        #pragma unroll 4
        for (int i = 0; i < Hk; i++) {
            const unsigned long long hb = pack2(h1[i], h1[i]);
            const ulonglong2* wr = (const ulonglong2*)(W2T + i * Hk);
            #pragma unroll
            for (int q = 0; q < 16; q++) {
                ulonglong2 wv = wr[q];
                acc[2 * q]     = fma2(wv.x, hb, acc[2 * q]);
                acc[2 * q + 1] = fma2(wv.y, hb, acc[2 * q + 1]);
            }
        }

        float skacc = g_skb[0];
        float* hout = g_h + (size_t)b * Hk * NN + j;
        #pragma unroll
        for (int q = 0; q < 32; q++) {
            float2 v = unpack2(acc[q]);
            float a0 = fmaxf(v.x, 0.f), a1 = fmaxf(v.y, 0.f);
            hout[(size_t)(2 * q) * NN] = a0;
            hout[(size_t)(2 * q + 1) * NN] = a1;
            skacc += a0 * kvs[2 * q] + a1 * kvs[2 * q + 1];
        }
        g_sk[b * NN + j] = skacc;
    } else if (j == Nk) {
        // output node: relu(Wenc @ output_xx[b,0,:] + benc)
        float x[8];
        const float* xp = oxx + b * 8;
        #pragma unroll
        for (int i = 0; i < 8; i++) x[i] = xp[i];
        float skacc = g_skb[0];
        float* hout = g_h + (size_t)b * Hk * NN + j;
        #pragma unroll
        for (int o = 0; o < Hk; o++) {
            float acc = bencs[o];
            #pragma unroll
            for (int i = 0; i < 8; i++) acc += WencT[i * Hk + o] * x[i];
            acc = fmaxf(acc, 0.f);
            hout[(size_t)o * NN] = acc;
            skacc += acc * kvs[o];
        }
        g_sk[b * NN + j] = skacc;
    }
}

// ---------------------------------------------------------------------------
// K23: fused softmax + weighted reduce.  grid (8, 32) = (o-group, b), 256 thr.
//      Each block recomputes softmax for its b (cheap, L2-hot), then reduces
//      8 h-rows with float4 loads (12 LDG.128 MLP per thread).
// ---------------------------------------------------------------------------
__global__ __launch_bounds__(256) void k23_softmax_reduce() {
    const int og = blockIdx.x, b = blockIdx.y;
    const int tid = threadIdx.x;
    const int lane = tid & 31, warp = tid >> 5;
    __shared__ __align__(16) float wsh[NN];
    __shared__ float red[8];

    // softmax over sk[b][:]
    float vals[6];
    float mx = -1e30f;
    #pragma unroll
    for (int t = 0; t < 6; t++) {
        vals[t] = g_sk[b * NN + t * 256 + tid];
        mx = fmaxf(mx, vals[t]);
    }
    #pragma unroll
    for (int s = 16; s > 0; s >>= 1) mx = fmaxf(mx, __shfl_xor_sync(0xffffffffu, mx, s));
    if (lane == 0) red[warp] = mx;
    __syncthreads();
    if (tid == 0) {
        float m = red[0];
        #pragma unroll
        for (int w = 1; w < 8; w++) m = fmaxf(m, red[w]);
        red[0] = m;
    }
    __syncthreads();
    mx = red[0];
    __syncthreads();

    float sum = 0.f;
    #pragma unroll
    for (int t = 0; t < 6; t++) { vals[t] = __expf(vals[t] - mx); sum += vals[t]; }
    #pragma unroll
    for (int s = 16; s > 0; s >>= 1) sum += __shfl_xor_sync(0xffffffffu, sum, s);
    if (lane == 0) red[warp] = sum;
    __syncthreads();
    if (tid == 0) {
        float s = 0.f;
        #pragma unroll
        for (int w = 0; w < 8; w++) s += red[w];
        red[0] = 1.f / s;
    }
    __syncthreads();
    const float inv = red[0];
    #pragma unroll
    for (int t = 0; t < 6; t++) wsh[t * 256 + tid] = vals[t] * inv;
    __syncthreads();

    // weighted reduce: m[b][o] = sum_j w[j] * h[b][o][j], 8 rows per block
    const int ol = tid >> 5;             // 0..7
    const int o = og * 8 + ol;
    const float4* hp = (const float4*)(g_h + ((size_t)b * Hk + o) * NN);
    const float4* wp = (const float4*)wsh;
    float acc = 0.f;
    #pragma unroll
    for (int k = 0; k < 12; k++) {
        float4 hv = hp[lane + 32 * k];
        float4 wv = wp[lane + 32 * k];
        acc += hv.x * wv.x + hv.y * wv.y + hv.z * wv.z + hv.w * wv.w;
    }
    #pragma unroll
    for (int s = 16; s > 0; s >>= 1) acc += __shfl_down_sync(0xffffffffu, acc, s);
    if (lane == 0) g_m[b * Hk + o] = acc;
}

// ---------------------------------------------------------------------------
// K4: collapsed rounds with fused Wc = WA@WV: each round is ONE gemm
//     z = n @ Wc^T + bc, then BN + relu.  Wc row lives in registers (packed),
//     reused across all 4 rounds.  1 block, 512 thr.
// ---------------------------------------------------------------------------
__global__ __launch_bounds__(512) void k4_tail(
    const float* __restrict__ gamma, const float* __restrict__ beta,
    const float* __restrict__ Wmu, const float* __restrict__ bmu,
    const float* __restrict__ Wsig, const float* __restrict__ bsig,
    float* __restrict__ out) {
    __shared__ __align__(16) float ns[Bk * Hk];   // [b][h]
    __shared__ float sc[Hk], sh[Hk];

    const int tid = threadIdx.x;
    const int h = tid & 63;
    const int bg = tid >> 6;     // 0..7

    // preload Wc row h into registers (packed o-pairs); L2-hot from k0
    unsigned long long w[32];
    {
        const ulonglong2* wr = (const ulonglong2*)(g_Wc + h * Hk);
        #pragma unroll
        for (int q = 0; q < 16; q++) { ulonglong2 v = wr[q]; w[2 * q] = v.x; w[2 * q + 1] = v.y; }
    }
    const float bch = g_bc[h];

    for (int t = tid; t < Bk * Hk; t += 512) ns[t] = g_m[t];
    __syncthreads();

    const int b0 = bg, b1 = bg + 8, b2 = bg + 16, b3 = bg + 24;

    for (int r = 0; r < 4; r++) {
        unsigned long long a0 = 0ull, a1 = 0ull, a2 = 0ull, a3 = 0ull;
        #pragma unroll
        for (int q = 0; q < 16; q++) {
            // uniform broadcasts of n quads (4 o's) per b
            ulonglong2 n0 = *(const ulonglong2*)(ns + b0 * Hk + 4 * q);
            ulonglong2 n1 = *(const ulonglong2*)(ns + b1 * Hk + 4 * q);
            ulonglong2 n2 = *(const ulonglong2*)(ns + b2 * Hk + 4 * q);
            ulonglong2 n3 = *(const ulonglong2*)(ns + b3 * Hk + 4 * q);
            a0 = fma2(w[2 * q], n0.x, a0); a0 = fma2(w[2 * q + 1], n0.y, a0);
            a1 = fma2(w[2 * q], n1.x, a1); a1 = fma2(w[2 * q + 1], n1.y, a1);
            a2 = fma2(w[2 * q], n2.x, a2); a2 = fma2(w[2 * q + 1], n2.y, a2);
            a3 = fma2(w[2 * q], n3.x, a3); a3 = fma2(w[2 * q + 1], n3.y, a3);
        }
        float2 v0 = unpack2(a0), v1 = unpack2(a1), v2 = unpack2(a2), v3 = unpack2(a3);
        const float z0 = v0.x + v0.y + bch;
        const float z1 = v1.x + v1.y + bch;
        const float z2 = v2.x + v2.y + bch;
        const float z3 = v3.x + v3.y + bch;
        __syncthreads();
        ns[b0 * Hk + h] = z0; ns[b1 * Hk + h] = z1;
        ns[b2 * Hk + h] = z2; ns[b3 * Hk + h] = z3;
        __syncthreads();

        // BatchNorm over batch (training mode, biased var)
        if (tid < Hk) {
            float s = 0.f, ss = 0.f;
            #pragma unroll 8
            for (int b = 0; b < Bk; b++) { float v = ns[b * Hk + tid]; s += v; ss += v * v; }
            float mu = s * (1.f / Bk);
            float var = ss * (1.f / Bk) - mu * mu;
            float scale = gamma[tid] * rsqrtf(var + 1e-5f);
            sc[tid] = scale;
            sh[tid] = beta[tid] - mu * scale;
        }
        __syncthreads();
        ns[b0 * Hk + h] = fmaxf(z0 * sc[h] + sh[h], 0.f);
        ns[b1 * Hk + h] = fmaxf(z1 * sc[h] + sh[h], 0.f);
        ns[b2 * Hk + h] = fmaxf(z2 * sc[h] + sh[h], 0.f);
        ns[b3 * Hk + h] = fmaxf(z3 * sc[h] + sh[h], 0.f);
        __syncthreads();
    }

    // Heads: agg = n (max over identical nodes)
    if (tid < Bk) {
        float m = bmu[0], s = bsig[0];
        #pragma unroll 8
        for (int hh = 0; hh < Hk; hh++) {
            float v = ns[tid * Hk + hh];
            m += v * Wmu[hh]; s += v * Wsig[hh];
        }
        out[tid] = m;
        out[Bk + tid] = s * s + 0.01f;
    }
}

// ---------------------------------------------------------------------------
extern "C" void kernel_launch(void* const* d_in, const int* in_sizes, int n_in,
                              void* d_out, int out_size) {
    const float* xx   = (const float*)d_in[0];   // input_xx  [32,1535,8]
    const float* yy   = (const float*)d_in[1];   // input_yy  [32,1535]
    const float* oxx  = (const float*)d_in[2];   // output_xx [32,1,8]
    const float* W1   = (const float*)d_in[3];
    const float* b1   = (const float*)d_in[4];
    const float* W2   = (const float*)d_in[5];
    const float* b2   = (const float*)d_in[6];
    const float* Wenc = (const float*)d_in[7];
    const float* benc = (const float*)d_in[8];
    // d_in[9], d_in[10] = WQ, bQ  (cancel in softmax -> unused)
    const float* WK   = (const float*)d_in[11];
    const float* bK   = (const float*)d_in[12];
    const float* WV   = (const float*)d_in[13];
    const float* bV   = (const float*)d_in[14];
    // d_in[15] = wQKq (cancels), d_in[17] = bQK (cancels)
    const float* wQKk = (const float*)d_in[16];
    const float* WA   = (const float*)d_in[18];
    const float* bA   = (const float*)d_in[19];
    const float* gamma= (const float*)d_in[20];
    const float* beta = (const float*)d_in[21];
    const float* Wmu  = (const float*)d_in[22];
    const float* bmu  = (const float*)d_in[23];
    const float* Wsig = (const float*)d_in[24];
    const float* bsig = (const float*)d_in[25];
    float* out = (float*)d_out;

    k0_prep<<<1, 1024>>>(WK, bK, wQKk, WA, bA, WV, bV);
    dim3 g1(12, 32);
    k1_encode<<<g1, 128>>>(xx, yy, oxx, W1, b1, W2, b2, Wenc, benc);
    dim3 g23(8, 32);
    k23_softmax_reduce<<<g23, 256>>>();
    k4_tail<<<1, 512>>>(gamma, beta, Wmu, bmu, Wsig, bsig, out);
}